// round 15
// baseline (speedup 1.0000x reference)
#include <cuda_runtime.h>
#include <cuda_fp16.h>
#include <cstdint>
#include <math.h>

// Problem constants
#define HN    1024
#define EMBD  512
#define VOC   32000
#define BB    16
#define SEQ   128
#define MROWS (BB*SEQ)   // 2048
#define G4    (4*HN)     // 4096

#define NCTA_LSTM 64
#define NCTA_ALL  148
// Work queue phases: XG tiles | W_fc cvt chunks | logits tiles
#define XG_MT     (MROWS/128)               // 16
#define XG_NT     (G4/128)                  // 32
#define Q_XG_END  (XG_MT*XG_NT)             // 512
#define CVT_CHUNKS (VOC/128)                // 250
#define Q_CVT_END (Q_XG_END + CVT_CHUNKS)   // 762
#define NTY       (VOC/128)                 // 250
#define NT_TILES  ((MROWS/128)*NTY)         // 4000
#define Q_TOTAL   (Q_CVT_END + NT_TILES)    // 4762

// Scratch (device globals: allocation-free). fp16 operands stored as packed
// half2 words (unsigned). g_Arows/g_XG/g_HS are T-MAJOR: row = t*16 + b.
__device__ float    g_XG[MROWS * G4];              // gate projections (t-major)
__device__ unsigned g_HS[MROWS * HN/2];            // hidden states (t-major)
__device__ unsigned g_Arows[MROWS * EMBD/2];       // gathered emb rows (t-major)
__device__ unsigned g_Wih_h[G4 * EMBD/2];          // W_ih fp16
__device__ unsigned g_Wfc_h[(size_t)VOC * HN/2];   // W_fc fp16 (filled by workers)
__device__ unsigned g_Hb[2][BB * HN/2];            // h double buffer
__device__ float    g_C[BB * HN];
// Sync state (each counter on its own 2KB-spread L2 line)
#define NCTR 8
#define CTR_STRIDE 512
__device__ unsigned g_ctrs[NCTR * CTR_STRIDE];     // LSTM barrier arrivals
__device__ unsigned g_prog[CTR_STRIDE];            // LSTM progress (steps done)
__device__ unsigned g_work[CTR_STRIDE];            // queue head
__device__ unsigned g_xgc[XG_MT * CTR_STRIDE];     // per-M-tile-group XG done
__device__ unsigned g_cvtc[CTR_STRIDE];            // W_fc cvt chunks done

__device__ __forceinline__ unsigned f2h2(float a, float b){
    __half2 h = __floats2half2_rn(a, b);
    return *reinterpret_cast<unsigned*>(&h);
}

#define MMA_F16(d, a0,a1,a2,a3, b0,b1) \
  asm volatile("mma.sync.aligned.m16n8k16.row.col.f32.f16.f16.f32 " \
    "{%0,%1,%2,%3}, {%4,%5,%6,%7}, {%8,%9}, {%0,%1,%2,%3};\n" \
    : "+f"(d[0]), "+f"(d[1]), "+f"(d[2]), "+f"(d[3]) \
    : "r"(a0), "r"(a1), "r"(a2), "r"(a3), "r"(b0), "r"(b1))

#define CP16(dst,src) asm volatile("cp.async.cg.shared.global [%0], [%1], 16;\n" :: "r"(dst), "l"(src))
#define CP_COMMIT()   asm volatile("cp.async.commit_group;\n")
#define CP_WAIT(n)    asm volatile("cp.async.wait_group %0;\n" :: "n"(n))
#define BARX(id)      asm volatile("bar.sync %0, %1;" :: "r"(id), "r"(256) : "memory")
#define LD_ACQ(v, p)  asm volatile("ld.acquire.gpu.global.u32 %0, [%1];" : "=r"(v) : "l"(p) : "memory")

// ============================================================================
// Small pre-kernels
// ============================================================================
__global__ void __launch_bounds__(256) cvt_f16_kernel(
    const float4* __restrict__ in, uint2* __restrict__ out, int n4)
{
    int i = blockIdx.x * blockDim.x + threadIdx.x;
    int stride = gridDim.x * blockDim.x;
    for (; i < n4; i += stride){
        float4 v = in[i];
        uint2 u; u.x = f2h2(v.x, v.y); u.y = f2h2(v.z, v.w);
        out[i] = u;
    }
}

// Gather-convert embedding rows into T-MAJOR layout: dst row = t*16 + b
__global__ void __launch_bounds__(128) gather_cvt_kernel(
    const float* __restrict__ emb, const int* __restrict__ tgt,
    unsigned* __restrict__ out)
{
    int r = blockIdx.x;                 // r = b*128 + t
    int b = r >> 7, t = r & 127;
    const float4* src = (const float4*)(emb + (size_t)tgt[r] * EMBD);
    uint2* dst = (uint2*)(out + (size_t)(t*BB + b) * (EMBD/2));
    int i = threadIdx.x;
    float4 v = src[i];
    uint2 u; u.x = f2h2(v.x, v.y); u.y = f2h2(v.z, v.w);
    dst[i] = u;
}

// ============================================================================
// Generic 128x128 fp16 GEMM tile (device fn, 256 threads, named barrier).
// MODE 0: XG   — A=g_Arows (Kw=256), B=g_Wih_h, C=g_XG fp32 += b_ih+b_hh
// MODE 1: logits — A=g_HS (Kw=512), B=g_Wfc_h, out += b_fc, permuted store
// Proven R9 body: 2-stage cp.async, LDS.128 k-permuted fragment loads.
// ============================================================================
template<int MODE>
__device__ void tile_gemm(unsigned* As, int barid, int tid, int bm0, int bn0,
                          const unsigned* __restrict__ A,
                          const unsigned* __restrict__ B,
                          int Kw, int N,
                          const float* __restrict__ bias0,
                          const float* __restrict__ bias1,
                          float* __restrict__ C)
{
    constexpr int BM=128, BKW=32, LD=36;
    unsigned* Bs = As + 2*BM*LD;
    const int lane = tid & 31, w = tid >> 5;
    const int mb = (w & 3) * 32;
    const int nb = (w >> 2) * 64;
    const int g  = lane >> 2, t4 = lane & 3;

    const unsigned* asrc[4]; unsigned adst[4];
    const unsigned* bsrc[4]; unsigned bdst[4];
    unsigned As_b = (unsigned)__cvta_generic_to_shared(As);
    unsigned Bs_b = (unsigned)__cvta_generic_to_shared(Bs);
    #pragma unroll
    for (int j=0;j<4;j++){
        int idx = tid + 256*j;
        int r = idx >> 3, c4 = idx & 7;
        asrc[j] = A + (size_t)(bm0 + r) * Kw + c4*4;
        adst[j] = As_b + (unsigned)((r*LD + c4*4) * 4);
        bsrc[j] = B + (size_t)(bn0 + r) * Kw + c4*4;
        bdst[j] = Bs_b + (unsigned)((r*LD + c4*4) * 4);
    }
    const unsigned stS = BM*LD*4;

    float acc[2][8][4];
    #pragma unroll
    for (int i=0;i<2;i++)
        #pragma unroll
        for (int j=0;j<8;j++)
            #pragma unroll
            for (int k=0;k<4;k++) acc[i][j][k]=0.f;

    const int niter = Kw / BKW;
    #pragma unroll
    for (int j=0;j<4;j++){ CP16(adst[j], asrc[j]); CP16(bdst[j], bsrc[j]); }
    CP_COMMIT();
    #pragma unroll
    for (int j=0;j<4;j++){ CP16(adst[j]+stS, asrc[j]+BKW); CP16(bdst[j]+stS, bsrc[j]+BKW); }
    CP_COMMIT();
    CP_WAIT(1);
    BARX(barid);

    for (int it=0; it<niter; it++){
        const int s = it & 1;
        const unsigned* As_ = As + s*BM*LD;
        const unsigned* Bs_ = Bs + s*BM*LD;
        #pragma unroll
        for (int kq=0; kq<2; kq++){
            uint4 a[2][2], b[8];
            #pragma unroll
            for (int mt=0; mt<2; mt++){
                const unsigned* p = As_ + (mb + mt*16 + g)*LD + t4*8 + kq*4;
                a[mt][0] = *(const uint4*)p;
                a[mt][1] = *(const uint4*)(p + 8*LD);
            }
            #pragma unroll
            for (int nt=0; nt<8; nt++)
                b[nt] = *(const uint4*)(Bs_ + (nb + nt*8 + g)*LD + t4*8 + kq*4);
            #pragma unroll
            for (int mt=0; mt<2; mt++)
                #pragma unroll
                for (int nt=0; nt<8; nt++){
                    MMA_F16(acc[mt][nt], a[mt][0].x, a[mt][1].x, a[mt][0].y, a[mt][1].y,
                            b[nt].x, b[nt].y);
                    MMA_F16(acc[mt][nt], a[mt][0].z, a[mt][1].z, a[mt][0].w, a[mt][1].w,
                            b[nt].z, b[nt].w);
                }
        }
        BARX(barid);
        if (it + 2 < niter){
            const int k0 = (it+2)*BKW;
            const unsigned so = (unsigned)s*stS;
            #pragma unroll
            for (int j=0;j<4;j++){ CP16(adst[j]+so, asrc[j]+k0); CP16(bdst[j]+so, bsrc[j]+k0); }
            CP_COMMIT();
            CP_WAIT(1);
        } else {
            CP_WAIT(0);
        }
        BARX(barid);
    }

    #pragma unroll
    for (int mt=0; mt<2; mt++){
        int row = bm0 + mb + mt*16 + g;
        #pragma unroll
        for (int nt=0; nt<8; nt++){
            int col = bn0 + nb + nt*8 + 2*t4;
            if (MODE == 0){
                float b0v = bias0[col] + bias1[col];
                float b1v = bias0[col+1] + bias1[col+1];
                float2 v0 = make_float2(acc[mt][nt][0] + b0v, acc[mt][nt][1] + b1v);
                float2 v1 = make_float2(acc[mt][nt][2] + b0v, acc[mt][nt][3] + b1v);
                *(float2*)(C + (size_t)row*N + col)     = v0;
                *(float2*)(C + (size_t)(row+8)*N + col) = v1;
            } else {
                // row = t*16 + b  ->  out[b][t][col]
                int tt  = row >> 4;
                int b0i = row & 15;
                float bv0 = bias0[col], bv1 = bias0[col+1];
                float2 v0 = make_float2(acc[mt][nt][0] + bv0, acc[mt][nt][1] + bv1);
                float2 v1 = make_float2(acc[mt][nt][2] + bv0, acc[mt][nt][3] + bv1);
                *(float2*)(C + ((size_t)b0i*SEQ + tt) * VOC + col)     = v0;
                *(float2*)(C + ((size_t)(b0i+8)*SEQ + tt) * VOC + col) = v1;
            }
        }
    }
}

// ============================================================================
// Worker loop: phases XG tiles -> W_fc cvt chunks -> logits tiles.
// ============================================================================
__device__ void worker_loop(unsigned* inst_smem, int barid, int tid,
                            volatile unsigned* smem_w,
                            const float* __restrict__ b_ih,
                            const float* __restrict__ b_hh,
                            const float* __restrict__ b_fc,
                            const float* __restrict__ W_fc,
                            float* __restrict__ out)
{
    for (;;){
        if (tid == 0){
            unsigned wk = atomicAdd(&g_work[0], 1u);
            *smem_w = wk;
        }
        BARX(barid);
        unsigned wk = *smem_w;
        BARX(barid);                 // all read before next overwrite
        if (wk >= (unsigned)Q_TOTAL) break;

        if (wk < Q_XG_END){
            // XG tile (t-major rows)
            int mt = wk >> 5, nt = wk & 31;
            tile_gemm<0>(inst_smem, barid, tid, mt*128, nt*128,
                         g_Arows, g_Wih_h, EMBD/2, G4, b_ih, b_hh, g_XG);
            BARX(barid);
            if (tid == 0){
                __threadfence();
                atomicAdd(&g_xgc[mt * CTR_STRIDE], 1u);
            }
        } else if (wk < Q_CVT_END){
            // W_fc cvt chunk: 128 vocab rows (128*256 float4)
            int ch = wk - Q_XG_END;
            const float4* src = (const float4*)W_fc + (size_t)ch*128*256;
            uint2* dst = (uint2*)g_Wfc_h + (size_t)ch*128*256;
            for (int i = tid; i < 128*256; i += 256){
                float4 v = src[i];
                uint2 u; u.x = f2h2(v.x, v.y); u.y = f2h2(v.z, v.w);
                dst[i] = u;
            }
            BARX(barid);
            if (tid == 0){
                __threadfence();
                atomicAdd(&g_cvtc[0], 1u);
            }
        } else {
            // logits tile: wait LSTM progress + cvt complete
            int lk = wk - Q_CVT_END;
            int mt = lk / NTY, nt = lk % NTY;
            if (tid == 0){
                const unsigned need = 8u*mt + 8u;
                unsigned v;
                for (;;){ LD_ACQ(v, &g_prog[0]); if (v >= need) break; __nanosleep(256); }
                for (;;){ LD_ACQ(v, &g_cvtc[0]); if (v >= (unsigned)CVT_CHUNKS) break; __nanosleep(256); }
            }
            BARX(barid);
            tile_gemm<1>(inst_smem, barid, tid, mt*128, nt*128,
                         g_HS, g_Wfc_h, HN/2, VOC, b_fc, nullptr, out);
        }
    }
}

// ============================================================================
// Fused persistent kernel: CTAs 0..63 = LSTM (R13 body, xg-gated, t-major HS);
// CTAs 64..147 = workers (2 x 8-warp GEMM instances). LSTM CTAs join the
// queue after the recurrence.
// ============================================================================
__global__ void __launch_bounds__(512) lstm_fused(
    const float* __restrict__ W_hh, const float* __restrict__ b_ih,
    const float* __restrict__ b_hh, const float* __restrict__ b_fc,
    const float* __restrict__ W_fc, float* __restrict__ out)
{
    extern __shared__ unsigned smem_u[];
    const int tid    = threadIdx.x;
    const int inst   = tid >> 8;
    const int tid256 = tid & 255;
    unsigned* inst_smem = smem_u + inst * (2*2*128*36);
    volatile unsigned* smem_w = smem_u + 2*(2*2*128*36) + inst;

    if (blockIdx.x >= NCTA_LSTM){
        worker_loop(inst_smem, 1+inst, tid256, smem_w, b_ih, b_hh, b_fc, W_fc, out);
        return;
    }

    // ---------------- LSTM role ----------------
    constexpr int HW  = HN/2;
    constexpr int LDW = HW + 4;
    unsigned* WsU = smem_u;              // [64][516]
    unsigned* HsU = WsU + 64*LDW;        // [16][516]
    float*    Gs  = (float*)(HsU + 16*LDW);  // [2][16][64]

    const int lane = tid & 31, w = tid >> 5;
    const int u0    = blockIdx.x * 16;
    const int rows8 = w & 7;
    const int half  = w >> 3;
    const int g    = lane >> 2, t4 = lane & 3;

    #pragma unroll 4
    for (int j=0;j<32;j++){
        int idx = tid + 512*j;
        int r = idx >> 8, c4 = idx & 255;
        int grow = (r>>4)*HN + u0 + (r&15);
        float4 v = *(const float4*)(W_hh + (size_t)grow*HN + c4*4);
        uint2 u; u.x = f2h2(v.x, v.y); u.y = f2h2(v.z, v.w);
        *(uint2*)(WsU + r*LDW + c4*2) = u;
    }

    for (int t=0; t<SEQ; t++){
        // gate on XG availability for this 8-step group
        if ((t & 7) == 0){
            if (tid == 0){
                unsigned v;
                const unsigned* ctr = &g_xgc[(t>>3) * CTR_STRIDE];
                for (;;){ LD_ACQ(v, ctr); if (v >= (unsigned)XG_NT) break; __nanosleep(128); }
            }
            __syncthreads();
        }

        // XG prefetch (t-major: row = t*16+b)
        float xgi=0.f, xgf=0.f, xgg=0.f, xgo=0.f;
        int bb=0, uu=0;
        if (tid < 256){
            bb = tid >> 4; uu = tid & 15;
            size_t xb = ((size_t)t*BB + bb)*G4 + u0 + uu;
            xgi = __ldg(&g_XG[xb]);
            xgf = __ldg(&g_XG[xb + HN]);
            xgg = __ldg(&g_XG[xb + 2*HN]);
            xgo = __ldg(&g_XG[xb + 3*HN]);
        }

        // grid barrier (R10/R13-proven)
        __syncthreads();
        if (tid == 0){
            __threadfence();
            atomicAdd(&g_ctrs[(blockIdx.x & (NCTR-1)) * CTR_STRIDE], 1u);
        }
        if (tid < NCTR){
            const unsigned target = (NCTA_LSTM/NCTR) * (unsigned)(t+1);
            unsigned v;
            for (;;){
                LD_ACQ(v, g_ctrs + tid*CTR_STRIDE);
                if (v >= target) break;
                __nanosleep(32);
            }
        }
        __syncthreads();
        if (blockIdx.x == 0 && tid == 0 && t > 0){
            asm volatile("st.release.gpu.global.u32 [%0], %1;"
                         :: "l"(&g_prog[0]), "r"((unsigned)t) : "memory");
        }

        const unsigned* hsrc = g_Hb[t & 1];
        #pragma unroll 4
        for (int j=0;j<4;j++){
            int idx = tid + 512*j;
            int r = idx >> 7, c = idx & 127;
            *(uint4*)(HsU + r*LDW + c*4) = *(const uint4*)(hsrc + r*HW + c*4);
        }
        __syncthreads();

        float acc0[4] = {0.f,0.f,0.f,0.f};
        float acc1[4] = {0.f,0.f,0.f,0.f};
        {
            const int ksw = half * (HW/2);
            const unsigned* hrow0 = HsU + g*LDW             + ksw + t4*8;
            const unsigned* hrow1 = HsU + (g+8)*LDW         + ksw + t4*8;
            const unsigned* wrow  = WsU + (rows8*8+g)*LDW   + ksw + t4*8;
            #pragma unroll 4
            for (int j=0; j<8; j++){
                const int base = j*32;
                uint4 a0  = *(const uint4*)(hrow0 + base);
                uint4 a0h = *(const uint4*)(hrow0 + base + 4);
                uint4 a1  = *(const uint4*)(hrow1 + base);
                uint4 a1h = *(const uint4*)(hrow1 + base + 4);
                uint4 b0  = *(const uint4*)(wrow  + base);
                uint4 b0h = *(const uint4*)(wrow  + base + 4);
                MMA_F16(acc0, a0.x,  a1.x,  a0.y,  a1.y,  b0.x,  b0.y);
                MMA_F16(acc1, a0.z,  a1.z,  a0.w,  a1.w,  b0.z,  b0.w);
                MMA_F16(acc0, a0h.x, a1h.x, a0h.y, a1h.y, b0h.x, b0h.y);
                MMA_F16(acc1, a0h.z, a1h.z, a0h.w, a1h.w, b0h.z, b0h.w);
            }
        }
        float* Gw = Gs + half*(16*64);
        Gw[g*64     + rows8*8 + 2*t4    ] = acc0[0] + acc1[0];
        Gw[g*64     + rows8*8 + 2*t4 + 1] = acc0[1] + acc1[1];
        Gw[(g+8)*64 + rows8*8 + 2*t4    ] = acc0[2] + acc1[2];
        Gw[(g+8)*64 + rows8*8 + 2*t4 + 1] = acc0[3] + acc1[3];
        __syncthreads();

        if (tid < 256){
            const float* G0 = Gs + bb*64;
            const float* G1 = Gs + 16*64 + bb*64;
            float vi = G0[uu]    + G1[uu]    + xgi;
            float vf = G0[16+uu] + G1[16+uu] + xgf;
            float vg = G0[32+uu] + G1[32+uu] + xgg;
            float vo = G0[48+uu] + G1[48+uu] + xgo;
            float iv = 1.f/(1.f + expf(-vi));
            float fv = 1.f/(1.f + expf(-vf));
            float gv = tanhf(vg);
            float ov = 1.f/(1.f + expf(-vo));
            int hi = bb*HN + u0 + uu;
            float cv = fv * g_C[hi] + iv * gv;
            float hv = ov * tanhf(cv);
            g_C[hi] = cv;
            __half hh = __float2half_rn(hv);
            ((__half*)g_Hb[(t+1) & 1])[hi] = hh;
            ((__half*)g_HS)[((size_t)t*BB + bb)*HN + u0 + uu] = hh;   // t-major
        }
    }

    // final arrival -> publish prog = SEQ, then join the queue
    __syncthreads();
    if (tid == 0){
        __threadfence();
        atomicAdd(&g_ctrs[(blockIdx.x & (NCTR-1)) * CTR_STRIDE], 1u);
    }
    if (blockIdx.x == 0){
        if (tid < NCTR){
            const unsigned target = (NCTA_LSTM/NCTR) * (unsigned)(SEQ+1);
            unsigned v;
            for (;;){
                LD_ACQ(v, g_ctrs + tid*CTR_STRIDE);
                if (v >= target) break;
                __nanosleep(32);
            }
        }
        __syncthreads();
        if (tid == 0){
            asm volatile("st.release.gpu.global.u32 [%0], %1;"
                         :: "l"(&g_prog[0]), "r"((unsigned)SEQ) : "memory");
        }
    }
    __syncthreads();
    worker_loop(inst_smem, 1+inst, tid256, smem_w, b_ih, b_hh, b_fc, W_fc, out);
}

// ============================================================================
// Launch
// ============================================================================
extern "C" void kernel_launch(void* const* d_in, const int* in_sizes, int n_in,
                              void* d_out, int out_size)
{
    const int*   tgt  = (const int*)  d_in[0];
    const float* h    = (const float*)d_in[1];
    const float* c    = (const float*)d_in[2];
    const float* emb  = (const float*)d_in[3];
    const float* W_ih = (const float*)d_in[4];
    const float* W_hh = (const float*)d_in[5];
    const float* b_ih = (const float*)d_in[6];
    const float* b_hh = (const float*)d_in[7];
    const float* W_fc = (const float*)d_in[8];
    const float* b_fc = (const float*)d_in[9];
    float* out = (float*)d_out;
    (void)in_sizes; (void)n_in; (void)out_size;

    void *pHb, *pC, *pCtrs, *pProg, *pWork, *pXgc, *pCvtc, *pAr, *pWih;
    cudaGetSymbolAddress(&pHb,   g_Hb);
    cudaGetSymbolAddress(&pC,    g_C);
    cudaGetSymbolAddress(&pCtrs, g_ctrs);
    cudaGetSymbolAddress(&pProg, g_prog);
    cudaGetSymbolAddress(&pWork, g_work);
    cudaGetSymbolAddress(&pXgc,  g_xgc);
    cudaGetSymbolAddress(&pCvtc, g_cvtc);
    cudaGetSymbolAddress(&pAr,   g_Arows);
    cudaGetSymbolAddress(&pWih,  g_Wih_h);

    cudaMemcpyAsync(pC, c, BB*HN*sizeof(float), cudaMemcpyDeviceToDevice);
    cudaMemsetAsync(pCtrs, 0, NCTR*CTR_STRIDE*sizeof(unsigned));
    cudaMemsetAsync(pProg, 0, sizeof(unsigned));
    cudaMemsetAsync(pWork, 0, sizeof(unsigned));
    cudaMemsetAsync(pXgc,  0, XG_MT*CTR_STRIDE*sizeof(unsigned));
    cudaMemsetAsync(pCvtc, 0, sizeof(unsigned));

    const int smem_f = (64*516 + 16*516)*4 + 2*16*64*4;   // 173,312 B
    cudaFuncSetAttribute(lstm_fused, cudaFuncAttributeMaxDynamicSharedMemorySize, smem_f);

    // 0) small conversions (h0, gathered emb rows t-major, W_ih)
    cvt_f16_kernel<<<16, 256>>>((const float4*)h, (uint2*)pHb, BB*HN/4);
    gather_cvt_kernel<<<MROWS, 128>>>(emb, tgt, (unsigned*)pAr);
    cvt_f16_kernel<<<1024, 256>>>((const float4*)W_ih, (uint2*)pWih, G4*EMBD/4);

    // 1) fused everything else: XG (queued) + LSTM + W_fc cvt (queued) + logits
    lstm_fused<<<NCTA_ALL, 512, smem_f>>>(W_hh, b_ih, b_hh, b_fc, W_fc, out);
}